// round 6
// baseline (speedup 1.0000x reference)
#include <cuda_runtime.h>
#include <cuda_bf16.h>
#include <cstdint>

// ============================================================================
// QuantizedPatternMatcher — bit-sliced popcount matcher with CSA compression.
//   q(v) = #edges v exceeds (3-bit code); matches[m,p] = #d q_x==q_pat
// eq-word = NOR-of-xors over 3 bitplanes (3 LOP3). R5: POPC is quarter-rate,
// so compress 3 eq-words via carry-save adder (s=xor3, c=maj3):
//   popc(e0)+popc(e1)+popc(e2) == popc(s) + 2*popc(c)   -> 11 popcs per 16 words
// Argmax fused: key = (cnt<<10)|(1023-p); atomicMax per m; last CTA converts.
// ============================================================================

static constexpr int M_TOTAL = 8192;
static constexpr int P_TOTAL = 1024;
static constexpr int D_DIM   = 512;
static constexpr int NW      = 16;              // u32 words per plane per row
static constexpr int TR      = 64;              // tile rows (both M and P)
static constexpr int MT      = M_TOTAL / TR;    // 128
static constexpr int PT      = P_TOTAL / TR;    // 16
static constexpr int TILE_U32 = NW * 3 * TR;    // 3072 u32 = 12 KB per tile
static constexpr int NCTAS   = MT * PT;         // 2048

__device__ __align__(16) uint32_t g_Acode[MT * TILE_U32];   // 1.5 MB
__device__ __align__(16) uint32_t g_Bcode[PT * TILE_U32];   // 192 KB
__device__ uint32_t g_key[M_TOTAL];
__device__ unsigned int g_ctr;

// NOR-of-xors via guaranteed 3-LOP3 chain.
__device__ __forceinline__ uint32_t eq3(uint32_t a0, uint32_t b0,
                                        uint32_t a1, uint32_t b1,
                                        uint32_t a2, uint32_t b2) {
    uint32_t x, y, z;
    asm("lop3.b32 %0, %1, %2, %3, 0x3C;" : "=r"(x) : "r"(a0), "r"(b0), "r"(0u)); // a^b
    asm("lop3.b32 %0, %1, %2, %3, 0xBE;" : "=r"(y) : "r"(a1), "r"(b1), "r"(x));  // (a^b)|c
    asm("lop3.b32 %0, %1, %2, %3, 0x41;" : "=r"(z) : "r"(a2), "r"(b2), "r"(y));  // ~((a^b)|c)
    return z;
}
__device__ __forceinline__ uint32_t xor3(uint32_t a, uint32_t b, uint32_t c) {
    uint32_t r;
    asm("lop3.b32 %0, %1, %2, %3, 0x96;" : "=r"(r) : "r"(a), "r"(b), "r"(c));
    return r;
}
__device__ __forceinline__ uint32_t maj3(uint32_t a, uint32_t b, uint32_t c) {
    uint32_t r;
    asm("lop3.b32 %0, %1, %2, %3, 0xE8;" : "=r"(r) : "r"(a), "r"(b), "r"(c));
    return r;
}

// ------------------------------------------------------------- encoding ----
// One warp per (row, word). Ballots build 3 bitplanes. Tile layout
// [tile][w][plane][row_local(64)] -> match kernel copies are uint4 streams.
// Block 0 additionally zeroes g_key / g_ctr for this replay.
__global__ void __launch_bounds__(256) encode_kernel(
    const float* __restrict__ x, const float* __restrict__ pat,
    const float* __restrict__ edges) {
    if (blockIdx.x == 0) {
        for (int i = threadIdx.x; i < M_TOTAL; i += 256) g_key[i] = 0u;
        if (threadIdx.x == 0) g_ctr = 0u;
    }
    int gw   = blockIdx.x * 8 + (threadIdx.x >> 5);
    int lane = threadIdx.x & 31;

    const float* src;
    uint32_t* dst;
    int row, w;
    if (gw < M_TOTAL * NW) {
        src = x;   dst = g_Acode; row = gw >> 4; w = gw & 15;
    } else {
        gw -= M_TOTAL * NW;
        src = pat; dst = g_Bcode; row = gw >> 4; w = gw & 15;
    }

    float e0 = __ldg(edges + 0), e1 = __ldg(edges + 1), e2 = __ldg(edges + 2),
          e3 = __ldg(edges + 3), e4 = __ldg(edges + 4), e5 = __ldg(edges + 5),
          e6 = __ldg(edges + 6);
    float v = __ldg(src + (size_t)row * D_DIM + w * 32 + lane);
    int q = (v > e0) + (v > e1) + (v > e2) + (v > e3) + (v > e4) + (v > e5) + (v > e6);

    unsigned b0 = __ballot_sync(0xffffffffu, q & 1);
    unsigned b1 = __ballot_sync(0xffffffffu, q & 2);
    unsigned b2 = __ballot_sync(0xffffffffu, q & 4);
    if (lane == 0) {
        int rt = row >> 6, rl = row & 63;
        uint32_t* base = dst + (size_t)rt * TILE_U32 + (w * 3) * TR + rl;
        base[0]      = b0;
        base[TR]     = b1;
        base[2 * TR] = b2;
    }
}

// --------------------------------------------------------------- matcher ----
// CTA = 64M x 64P tile, 256 threads (tx 0..15 p-group, ty 0..15 m-group),
// thread computes 4M x 4P. Words processed in groups of 3 through a CSA so
// only 11 of 16 popcounts survive. B loaded in 2-col halves to bound regs.
__global__ void __launch_bounds__(256, 2) match_kernel(float* __restrict__ out) {
    __shared__ uint32_t sA[TILE_U32];
    __shared__ uint32_t sB[TILE_U32];
    __shared__ bool s_last;

    const int tid = threadIdx.x;
    const int pt = blockIdx.x, mt = blockIdx.y;

    const uint4* gA = reinterpret_cast<const uint4*>(g_Acode + (size_t)mt * TILE_U32);
    const uint4* gB = reinterpret_cast<const uint4*>(g_Bcode + (size_t)pt * TILE_U32);
    uint4* s4A = reinterpret_cast<uint4*>(sA);
    uint4* s4B = reinterpret_cast<uint4*>(sB);
#pragma unroll
    for (int i = 0; i < TILE_U32 / 4; i += 256) {
        s4A[i + tid] = gA[i + tid];
        s4B[i + tid] = gB[i + tid];
    }
    __syncthreads();

    const int tx = tid & 15;
    const int ty = tid >> 4;

    uint32_t accS[4][4], accC[4][4];
#pragma unroll
    for (int mi = 0; mi < 4; mi++)
#pragma unroll
        for (int pi = 0; pi < 4; pi++) { accS[mi][pi] = 0; accC[mi][pi] = 0; }

    // 5 CSA groups of 3 words (w = 0,3,...,12), leftover word 15 below.
#pragma unroll 1
    for (int wg = 0; wg < 15; wg += 3) {
        uint32_t a[3][3][4];   // [word in group][plane][mi]
#pragma unroll
        for (int u = 0; u < 3; u++)
#pragma unroll
            for (int pl = 0; pl < 3; pl++) {
                uint4 av = *reinterpret_cast<const uint4*>(
                    &sA[((wg + u) * 3 + pl) * TR + ty * 4]);
                a[u][pl][0] = av.x; a[u][pl][1] = av.y;
                a[u][pl][2] = av.z; a[u][pl][3] = av.w;
            }
#pragma unroll
        for (int h = 0; h < 2; h++) {
            uint32_t b[3][3][2];   // [word][plane][pi-local]
#pragma unroll
            for (int u = 0; u < 3; u++)
#pragma unroll
                for (int pl = 0; pl < 3; pl++) {
                    uint2 bv = *reinterpret_cast<const uint2*>(
                        &sB[((wg + u) * 3 + pl) * TR + tx * 4 + h * 2]);
                    b[u][pl][0] = bv.x; b[u][pl][1] = bv.y;
                }
#pragma unroll
            for (int mi = 0; mi < 4; mi++)
#pragma unroll
                for (int pi = 0; pi < 2; pi++) {
                    uint32_t e0 = eq3(a[0][0][mi], b[0][0][pi],
                                      a[0][1][mi], b[0][1][pi],
                                      a[0][2][mi], b[0][2][pi]);
                    uint32_t e1 = eq3(a[1][0][mi], b[1][0][pi],
                                      a[1][1][mi], b[1][1][pi],
                                      a[1][2][mi], b[1][2][pi]);
                    uint32_t e2 = eq3(a[2][0][mi], b[2][0][pi],
                                      a[2][1][mi], b[2][1][pi],
                                      a[2][2][mi], b[2][2][pi]);
                    accS[mi][h * 2 + pi] += (uint32_t)__popc(xor3(e0, e1, e2));
                    accC[mi][h * 2 + pi] += (uint32_t)__popc(maj3(e0, e1, e2));
                }
        }
    }
    {   // leftover word w = 15
        uint32_t a[3][4];
#pragma unroll
        for (int pl = 0; pl < 3; pl++) {
            uint4 av = *reinterpret_cast<const uint4*>(&sA[(15 * 3 + pl) * TR + ty * 4]);
            a[pl][0] = av.x; a[pl][1] = av.y; a[pl][2] = av.z; a[pl][3] = av.w;
        }
        uint32_t b[3][4];
#pragma unroll
        for (int pl = 0; pl < 3; pl++) {
            uint4 bv = *reinterpret_cast<const uint4*>(&sB[(15 * 3 + pl) * TR + tx * 4]);
            b[pl][0] = bv.x; b[pl][1] = bv.y; b[pl][2] = bv.z; b[pl][3] = bv.w;
        }
#pragma unroll
        for (int mi = 0; mi < 4; mi++)
#pragma unroll
            for (int pi = 0; pi < 4; pi++)
                accS[mi][pi] += (uint32_t)__popc(
                    eq3(a[0][mi], b[0][pi], a[1][mi], b[1][pi], a[2][mi], b[2][pi]));
    }

    // key = (cnt<<10)|(1023-p): max == first-max (lowest index wins ties).
#pragma unroll
    for (int mi = 0; mi < 4; mi++) {
        uint32_t key = 0;
#pragma unroll
        for (int pi = 0; pi < 4; pi++) {
            uint32_t cnt = accS[mi][pi] + 2u * accC[mi][pi];
            int p = pt * TR + tx * 4 + pi;
            uint32_t k = (cnt << 10) | (uint32_t)(1023 - p);
            key = key > k ? key : k;
        }
#pragma unroll
        for (int off = 8; off >= 1; off >>= 1) {   // reduce over the 16 tx lanes
            uint32_t o = __shfl_xor_sync(0xffffffffu, key, off);
            key = key > o ? key : o;
        }
        if (tx == 0) {
            int m = mt * TR + ty * 4 + mi;
            atomicMax(&g_key[m], key);
        }
    }

    // Last CTA converts keys -> (best_patterns, match_scores).
    __threadfence();
    if (tid == 0)
        s_last = (atomicAdd(&g_ctr, 1u) == (unsigned)(NCTAS - 1));
    __syncthreads();
    if (s_last) {
        __threadfence();   // acquire all g_key updates
        for (int m = tid; m < M_TOTAL; m += 256) {
            uint32_t best = g_key[m];
            out[m]           = (float)(1023u - (best & 1023u));
            out[M_TOTAL + m] = (float)(best >> 10) * (1.0f / 512.0f);
        }
    }
}

// ---------------------------------------------------------------- launch ----
extern "C" void kernel_launch(void* const* d_in, const int* in_sizes, int n_in,
                              void* d_out, int out_size) {
    const float* x     = (const float*)d_in[0];
    const float* pat   = (const float*)d_in[1];
    const float* edges = (const float*)d_in[2];

    // (8192 + 1024) rows * 16 words = 147456 warps -> 18432 blocks of 8 warps
    encode_kernel<<<(M_TOTAL + P_TOTAL) * NW / 8, 256>>>(x, pat, edges);
    match_kernel<<<dim3(PT, MT), 256>>>((float*)d_out);
}

// round 7
// speedup vs baseline: 1.0545x; 1.0545x over previous
#include <cuda_runtime.h>
#include <cuda_bf16.h>
#include <cstdint>

// ============================================================================
// QuantizedPatternMatcher — bit-sliced popcount matcher, single persistent
// kernel (encode -> device barrier -> match -> device barrier -> output).
//   q(v) = #edges v exceeds (3-bit code); matches[m,p] = #d q_x==q_pat
// Per u32 word (32 dims): eq = LOP3-chain(a0^b0,a1^b1,a2^b2) -> popc -> add.
// alu-pipe bound at ~5 ops / word-pair (proven floor); this round removes the
// non-compute overhead: launch count, wave tail, serialized finalize.
// Argmax exact: key = (cnt<<10)|(1023-p); max == first-max tie-breaking.
// ============================================================================

static constexpr int M_TOTAL = 8192;
static constexpr int P_TOTAL = 1024;
static constexpr int D_DIM   = 512;
static constexpr int NW      = 16;              // u32 words per plane per row
static constexpr int TR      = 64;              // tile rows (both M and P)
static constexpr int MT      = M_TOTAL / TR;    // 128
static constexpr int PT      = P_TOTAL / TR;    // 16
static constexpr int TILE_U32 = NW * 3 * TR;    // 3072 u32 = 12 KB per tile
static constexpr int NTILES  = MT * PT;         // 2048
static constexpr int NCTA    = 296;             // 2 CTAs/SM x 148 SMs, all resident
static constexpr int NJOBS   = (M_TOTAL + P_TOTAL) * NW;  // encode warp-jobs

__device__ __align__(16) uint32_t g_Acode[MT * TILE_U32];   // 1.5 MB
__device__ __align__(16) uint32_t g_Bcode[PT * TILE_U32];   // 192 KB
__device__ uint32_t g_key[M_TOTAL];
__device__ unsigned g_bar1, g_bar2, g_fin;
__device__ volatile unsigned g_go1, g_go2;

// NOR-of-xors via guaranteed 3-LOP3 chain.
__device__ __forceinline__ uint32_t eq3(uint32_t a0, uint32_t b0,
                                        uint32_t a1, uint32_t b1,
                                        uint32_t a2, uint32_t b2) {
    uint32_t x, y, z;
    asm("lop3.b32 %0, %1, %2, %3, 0x3C;" : "=r"(x) : "r"(a0), "r"(b0), "r"(0u)); // a^b
    asm("lop3.b32 %0, %1, %2, %3, 0xBE;" : "=r"(y) : "r"(a1), "r"(b1), "r"(x));  // (a^b)|c
    asm("lop3.b32 %0, %1, %2, %3, 0x41;" : "=r"(z) : "r"(a2), "r"(b2), "r"(y));  // ~((a^b)|c)
    return z;
}

// Device-wide barrier across all NCTA resident CTAs (spin, tid0 + bar.sync).
__device__ __forceinline__ void grid_barrier(unsigned* ctr, volatile unsigned* flag,
                                             int tid) {
    __syncthreads();
    __threadfence();
    if (tid == 0) {
        if (atomicAdd(ctr, 1u) + 1u == (unsigned)NCTA)
            atomicExch((unsigned*)flag, 1u);
        while (*flag == 0u) __nanosleep(64);
    }
    __syncthreads();
    __threadfence();
}

__global__ void __launch_bounds__(256, 2) fused_kernel(
    const float* __restrict__ x, const float* __restrict__ pat,
    const float* __restrict__ edges, float* __restrict__ out) {
    __shared__ uint32_t sA[TILE_U32];
    __shared__ uint32_t sB[TILE_U32];

    const int tid  = threadIdx.x;
    const int cta  = blockIdx.x;
    const int lane = tid & 31;

    // ---- phase 0: zero argmax keys (sliced across CTAs) ----
    for (int i = cta * 256 + tid; i < M_TOTAL; i += NCTA * 256) g_key[i] = 0u;

    // ---- phase 1: encode bitplanes (one warp-job = one (row, word)) ----
    {
        const float e0 = __ldg(edges + 0), e1 = __ldg(edges + 1),
                    e2 = __ldg(edges + 2), e3 = __ldg(edges + 3),
                    e4 = __ldg(edges + 4), e5 = __ldg(edges + 5),
                    e6 = __ldg(edges + 6);
        for (int j = cta * 8 + (tid >> 5); j < NJOBS; j += NCTA * 8) {
            int row = j >> 4, w = j & 15;
            const float* src = x;
            uint32_t* dst = g_Acode;
            int r = row;
            if (row >= M_TOTAL) { src = pat; dst = g_Bcode; r = row - M_TOTAL; }
            float v = __ldg(src + (size_t)r * D_DIM + w * 32 + lane);
            int q = (v > e0) + (v > e1) + (v > e2) + (v > e3) +
                    (v > e4) + (v > e5) + (v > e6);
            unsigned b0 = __ballot_sync(0xffffffffu, q & 1);
            unsigned b1 = __ballot_sync(0xffffffffu, q & 2);
            unsigned b2 = __ballot_sync(0xffffffffu, q & 4);
            if (lane == 0) {
                uint32_t* base = dst + (size_t)(r >> 6) * TILE_U32 + (w * 3) * TR + (r & 63);
                base[0]      = b0;
                base[TR]     = b1;
                base[2 * TR] = b2;
            }
        }
    }

    grid_barrier(&g_bar1, &g_go1, tid);

    // ---- phase 2: match tiles [t0, t1), m-major so sA is reused across pt ----
    const int t0 = (cta * NTILES) / NCTA;
    const int t1 = ((cta + 1) * NTILES) / NCTA;
    const int tx = tid & 15;
    const int ty = tid >> 4;
    int cur_mt = -1;

    for (int t = t0; t < t1; t++) {
        const int mt = t >> 4, pt = t & 15;

        if (mt != cur_mt) {   // uniform branch (t uniform across block)
            const uint4* gA = reinterpret_cast<const uint4*>(g_Acode + (size_t)mt * TILE_U32);
            uint4* s4A = reinterpret_cast<uint4*>(sA);
#pragma unroll
            for (int i = 0; i < TILE_U32 / 4; i += 256) s4A[i + tid] = gA[i + tid];
            cur_mt = mt;
        }
        {
            const uint4* gB = reinterpret_cast<const uint4*>(g_Bcode + (size_t)pt * TILE_U32);
            uint4* s4B = reinterpret_cast<uint4*>(sB);
#pragma unroll
            for (int i = 0; i < TILE_U32 / 4; i += 256) s4B[i + tid] = gB[i + tid];
        }
        __syncthreads();

        uint32_t acc[4][4];
#pragma unroll
        for (int mi = 0; mi < 4; mi++)
#pragma unroll
            for (int pi = 0; pi < 4; pi++) acc[mi][pi] = 0;

#pragma unroll 2
        for (int w = 0; w < NW; w++) {
            uint32_t a[3][4], b[3][4];
#pragma unroll
            for (int pl = 0; pl < 3; pl++) {
                const int rowbase = (w * 3 + pl) * TR;
                uint4 av = *reinterpret_cast<const uint4*>(&sA[rowbase + ty * 4]);
                a[pl][0] = av.x; a[pl][1] = av.y; a[pl][2] = av.z; a[pl][3] = av.w;
                uint4 bv = *reinterpret_cast<const uint4*>(&sB[rowbase + tx * 4]);
                b[pl][0] = bv.x; b[pl][1] = bv.y; b[pl][2] = bv.z; b[pl][3] = bv.w;
            }
#pragma unroll
            for (int mi = 0; mi < 4; mi++)
#pragma unroll
                for (int pi = 0; pi < 4; pi++)
                    acc[mi][pi] += (uint32_t)__popc(
                        eq3(a[0][mi], b[0][pi], a[1][mi], b[1][pi],
                            a[2][mi], b[2][pi]));
        }

        // key = (cnt<<10)|(1023-p): max == first-max (lowest index wins ties).
#pragma unroll
        for (int mi = 0; mi < 4; mi++) {
            uint32_t key = 0;
#pragma unroll
            for (int pi = 0; pi < 4; pi++) {
                int p = pt * TR + tx * 4 + pi;
                uint32_t k = (acc[mi][pi] << 10) | (uint32_t)(1023 - p);
                key = key > k ? key : k;
            }
#pragma unroll
            for (int off = 8; off >= 1; off >>= 1) {
                uint32_t o = __shfl_xor_sync(0xffffffffu, key, off);
                key = key > o ? key : o;
            }
            if (tx == 0)
                atomicMax(&g_key[mt * TR + ty * 4 + mi], key);
        }
        __syncthreads();   // tile done before smem overwrite next iteration
    }

    grid_barrier(&g_bar2, &g_go2, tid);

    // ---- phase 3: write outputs (sliced across CTAs) ----
    for (int m = cta * 256 + tid; m < M_TOTAL; m += NCTA * 256) {
        uint32_t best = g_key[m];
        out[m]           = (float)(1023u - (best & 1023u));          // best_patterns
        out[M_TOTAL + m] = (float)(best >> 10) * (1.0f / 512.0f);    // match_scores
    }

    // ---- cleanup: last CTA resets barrier state for the next graph replay ----
    __syncthreads();
    if (tid == 0) {
        if (atomicAdd(&g_fin, 1u) + 1u == (unsigned)NCTA) {
            g_bar1 = 0u; g_bar2 = 0u; g_fin = 0u;
            g_go1 = 0u;  g_go2 = 0u;
            __threadfence();
        }
    }
}

// ---------------------------------------------------------------- launch ----
extern "C" void kernel_launch(void* const* d_in, const int* in_sizes, int n_in,
                              void* d_out, int out_size) {
    const float* x     = (const float*)d_in[0];
    const float* pat   = (const float*)d_in[1];
    const float* edges = (const float*)d_in[2];

    fused_kernel<<<NCTA, 256>>>(x, pat, edges, (float*)d_out);
}

// round 8
// speedup vs baseline: 1.0987x; 1.0418x over previous
#include <cuda_runtime.h>
#include <cuda_bf16.h>
#include <cstdint>

// ============================================================================
// QuantizedPatternMatcher — bit-sliced popcount matcher.
//   q(v) = #edges v exceeds (3-bit code); matches[m,p] = #d q_x==q_pat
// Per u32 word (32 dims): eq = LOP3-chain(a0^b0,a1^b1,a2^b2) -> popc -> add.
// R7: register double-buffered software pipeline in the match loop — LDS for
// word w+1 issued before the 72-op alu block for word w, hiding the 29-cycle
// shared-memory latency behind independent compute.
// Argmax exact: key = (cnt<<10)|(1023-p); max == first-max tie-breaking.
// ============================================================================

static constexpr int M_TOTAL = 8192;
static constexpr int P_TOTAL = 1024;
static constexpr int D_DIM   = 512;
static constexpr int NW      = 16;              // u32 words per plane per row
static constexpr int TR      = 64;              // tile rows (both M and P)
static constexpr int MT      = M_TOTAL / TR;    // 128
static constexpr int PT      = P_TOTAL / TR;    // 16
static constexpr int TILE_U32 = NW * 3 * TR;    // 3072 u32 = 12 KB per tile
static constexpr int NCTAS   = MT * PT;         // 2048

__device__ __align__(16) uint32_t g_Acode[MT * TILE_U32];   // 1.5 MB
__device__ __align__(16) uint32_t g_Bcode[PT * TILE_U32];   // 192 KB
__device__ uint32_t g_key[M_TOTAL];
__device__ unsigned int g_ctr;

// NOR-of-xors via guaranteed 3-LOP3 chain.
__device__ __forceinline__ uint32_t eq3(uint32_t a0, uint32_t b0,
                                        uint32_t a1, uint32_t b1,
                                        uint32_t a2, uint32_t b2) {
    uint32_t x, y, z;
    asm("lop3.b32 %0, %1, %2, %3, 0x3C;" : "=r"(x) : "r"(a0), "r"(b0), "r"(0u)); // a^b
    asm("lop3.b32 %0, %1, %2, %3, 0xBE;" : "=r"(y) : "r"(a1), "r"(b1), "r"(x));  // (a^b)|c
    asm("lop3.b32 %0, %1, %2, %3, 0x41;" : "=r"(z) : "r"(a2), "r"(b2), "r"(y));  // ~((a^b)|c)
    return z;
}

struct Frag {
    uint32_t a[3][4];
    uint32_t b[3][4];
};

// ------------------------------------------------------------- encoding ----
// One warp per (row, word). Ballots build 3 bitplanes. Tile layout
// [tile][w][plane][row_local(64)] -> match kernel copies are uint4 streams.
// Block 0 additionally zeroes g_key / g_ctr for this replay.
__global__ void __launch_bounds__(256) encode_kernel(
    const float* __restrict__ x, const float* __restrict__ pat,
    const float* __restrict__ edges) {
    if (blockIdx.x == 0) {
        for (int i = threadIdx.x; i < M_TOTAL; i += 256) g_key[i] = 0u;
        if (threadIdx.x == 0) g_ctr = 0u;
    }
    int gw   = blockIdx.x * 8 + (threadIdx.x >> 5);
    int lane = threadIdx.x & 31;

    const float* src;
    uint32_t* dst;
    int row, w;
    if (gw < M_TOTAL * NW) {
        src = x;   dst = g_Acode; row = gw >> 4; w = gw & 15;
    } else {
        gw -= M_TOTAL * NW;
        src = pat; dst = g_Bcode; row = gw >> 4; w = gw & 15;
    }

    float e0 = __ldg(edges + 0), e1 = __ldg(edges + 1), e2 = __ldg(edges + 2),
          e3 = __ldg(edges + 3), e4 = __ldg(edges + 4), e5 = __ldg(edges + 5),
          e6 = __ldg(edges + 6);
    float v = __ldg(src + (size_t)row * D_DIM + w * 32 + lane);
    int q = (v > e0) + (v > e1) + (v > e2) + (v > e3) + (v > e4) + (v > e5) + (v > e6);

    unsigned b0 = __ballot_sync(0xffffffffu, q & 1);
    unsigned b1 = __ballot_sync(0xffffffffu, q & 2);
    unsigned b2 = __ballot_sync(0xffffffffu, q & 4);
    if (lane == 0) {
        int rt = row >> 6, rl = row & 63;
        uint32_t* base = dst + (size_t)rt * TILE_U32 + (w * 3) * TR + rl;
        base[0]      = b0;
        base[TR]     = b1;
        base[2 * TR] = b2;
    }
}

// --------------------------------------------------------------- matcher ----
// CTA = 64M x 64P tile, 256 threads (tx 0..15 p-group, ty 0..15 m-group),
// thread computes 4M x 4P. Register ping-pong: loads for word w+1 issue
// before the alu block for word w (unroll-2, no register moves).
__global__ void __launch_bounds__(256) match_kernel(float* __restrict__ out) {
    __shared__ uint32_t sA[TILE_U32];
    __shared__ uint32_t sB[TILE_U32];
    __shared__ bool s_last;

    const int tid = threadIdx.x;
    const int pt = blockIdx.x, mt = blockIdx.y;

    const uint4* gA = reinterpret_cast<const uint4*>(g_Acode + (size_t)mt * TILE_U32);
    const uint4* gB = reinterpret_cast<const uint4*>(g_Bcode + (size_t)pt * TILE_U32);
    uint4* s4A = reinterpret_cast<uint4*>(sA);
    uint4* s4B = reinterpret_cast<uint4*>(sB);
#pragma unroll
    for (int i = 0; i < TILE_U32 / 4; i += 256) {
        s4A[i + tid] = gA[i + tid];
        s4B[i + tid] = gB[i + tid];
    }
    __syncthreads();

    const int tx = tid & 15;
    const int ty = tid >> 4;

    uint32_t acc[4][4];
#pragma unroll
    for (int mi = 0; mi < 4; mi++)
#pragma unroll
        for (int pi = 0; pi < 4; pi++) acc[mi][pi] = 0;

    Frag f0, f1;

    auto load_frag = [&](Frag& f, int w) {
#pragma unroll
        for (int pl = 0; pl < 3; pl++) {
            const int rowbase = (w * 3 + pl) * TR;
            uint4 av = *reinterpret_cast<const uint4*>(&sA[rowbase + ty * 4]);
            f.a[pl][0] = av.x; f.a[pl][1] = av.y; f.a[pl][2] = av.z; f.a[pl][3] = av.w;
            uint4 bv = *reinterpret_cast<const uint4*>(&sB[rowbase + tx * 4]);
            f.b[pl][0] = bv.x; f.b[pl][1] = bv.y; f.b[pl][2] = bv.z; f.b[pl][3] = bv.w;
        }
    };
    auto compute = [&](const Frag& f) {
#pragma unroll
        for (int mi = 0; mi < 4; mi++)
#pragma unroll
            for (int pi = 0; pi < 4; pi++)
                acc[mi][pi] += (uint32_t)__popc(
                    eq3(f.a[0][mi], f.b[0][pi], f.a[1][mi], f.b[1][pi],
                        f.a[2][mi], f.b[2][pi]));
    };

    load_frag(f0, 0);
#pragma unroll 1
    for (int w = 0; w < NW; w += 2) {
        load_frag(f1, w + 1);        // prefetch w+1, hidden behind compute(w)
        compute(f0);
        load_frag(f0, (w + 2) & 15); // prefetch w+2 (dummy wrap on last iter)
        compute(f1);
    }

    // key = (cnt<<10)|(1023-p): max == first-max (lowest index wins ties).
#pragma unroll
    for (int mi = 0; mi < 4; mi++) {
        uint32_t key = 0;
#pragma unroll
        for (int pi = 0; pi < 4; pi++) {
            int p = pt * TR + tx * 4 + pi;
            uint32_t k = (acc[mi][pi] << 10) | (uint32_t)(1023 - p);
            key = key > k ? key : k;
        }
#pragma unroll
        for (int off = 8; off >= 1; off >>= 1) {   // reduce over the 16 tx lanes
            uint32_t o = __shfl_xor_sync(0xffffffffu, key, off);
            key = key > o ? key : o;
        }
        if (tx == 0) {
            int m = mt * TR + ty * 4 + mi;
            atomicMax(&g_key[m], key);
        }
    }

    // Last CTA converts keys -> (best_patterns, match_scores).
    __threadfence();
    if (tid == 0)
        s_last = (atomicAdd(&g_ctr, 1u) == (unsigned)(NCTAS - 1));
    __syncthreads();
    if (s_last) {
        __threadfence();   // acquire all g_key updates
        for (int m = tid; m < M_TOTAL; m += 256) {
            uint32_t best = g_key[m];
            out[m]           = (float)(1023u - (best & 1023u));
            out[M_TOTAL + m] = (float)(best >> 10) * (1.0f / 512.0f);
        }
    }
}

// ---------------------------------------------------------------- launch ----
extern "C" void kernel_launch(void* const* d_in, const int* in_sizes, int n_in,
                              void* d_out, int out_size) {
    const float* x     = (const float*)d_in[0];
    const float* pat   = (const float*)d_in[1];
    const float* edges = (const float*)d_in[2];

    // (8192 + 1024) rows * 16 words = 147456 warps -> 18432 blocks of 8 warps
    encode_kernel<<<(M_TOTAL + P_TOTAL) * NW / 8, 256>>>(x, pat, edges);
    match_kernel<<<dim3(PT, MT), 256>>>((float*)d_out);
}

// round 9
// speedup vs baseline: 1.1113x; 1.0115x over previous
#include <cuda_runtime.h>
#include <cuda_bf16.h>
#include <cstdint>

// ============================================================================
// QuantizedPatternMatcher — bit-sliced popcount matcher.
//   q(v) = #edges v exceeds (3-bit code); matches[m,p] = #d q_x==q_pat
// Per u32 word (32 dims): eq = LOP3-chain(a0^b0,a1^b1,a2^b2) -> popc -> mad.
// R8: the alu pipe (rt=2) is the proven wall (alu% pinned at its 50% issue
// ceiling in every variant). Accumulation moved to the idle fma pipe via
// mad.lo.u32 with an opaque multiplier (kernel arg) so ptxas emits IMAD
// (fma-pipe) instead of IADD3 (alu-pipe): -20% alu ops per word.
// Argmax exact: key = (cnt<<10)|(1023-p); max == first-max tie-breaking.
// ============================================================================

static constexpr int M_TOTAL = 8192;
static constexpr int P_TOTAL = 1024;
static constexpr int D_DIM   = 512;
static constexpr int NW      = 16;              // u32 words per plane per row
static constexpr int TR      = 64;              // tile rows (both M and P)
static constexpr int MT      = M_TOTAL / TR;    // 128
static constexpr int PT      = P_TOTAL / TR;    // 16
static constexpr int TILE_U32 = NW * 3 * TR;    // 3072 u32 = 12 KB per tile
static constexpr int NCTAS   = MT * PT;         // 2048

__device__ __align__(16) uint32_t g_Acode[MT * TILE_U32];   // 1.5 MB
__device__ __align__(16) uint32_t g_Bcode[PT * TILE_U32];   // 192 KB
__device__ uint32_t g_key[M_TOTAL];
__device__ unsigned int g_ctr;

// NOR-of-xors via guaranteed 3-LOP3 chain.
__device__ __forceinline__ uint32_t eq3(uint32_t a0, uint32_t b0,
                                        uint32_t a1, uint32_t b1,
                                        uint32_t a2, uint32_t b2) {
    uint32_t x, y, z;
    asm("lop3.b32 %0, %1, %2, %3, 0x3C;" : "=r"(x) : "r"(a0), "r"(b0), "r"(0u)); // a^b
    asm("lop3.b32 %0, %1, %2, %3, 0xBE;" : "=r"(y) : "r"(a1), "r"(b1), "r"(x));  // (a^b)|c
    asm("lop3.b32 %0, %1, %2, %3, 0x41;" : "=r"(z) : "r"(a2), "r"(b2), "r"(y));  // ~((a^b)|c)
    return z;
}

struct Frag {
    uint32_t a[3][4];
    uint32_t b[3][4];
};

// ------------------------------------------------------------- encoding ----
// One warp per (row, word). Ballots build 3 bitplanes. Tile layout
// [tile][w][plane][row_local(64)] -> match kernel copies are uint4 streams.
// Block 0 additionally zeroes g_key / g_ctr for this replay.
__global__ void __launch_bounds__(256) encode_kernel(
    const float* __restrict__ x, const float* __restrict__ pat,
    const float* __restrict__ edges) {
    if (blockIdx.x == 0) {
        for (int i = threadIdx.x; i < M_TOTAL; i += 256) g_key[i] = 0u;
        if (threadIdx.x == 0) g_ctr = 0u;
    }
    int gw   = blockIdx.x * 8 + (threadIdx.x >> 5);
    int lane = threadIdx.x & 31;

    const float* src;
    uint32_t* dst;
    int row, w;
    if (gw < M_TOTAL * NW) {
        src = x;   dst = g_Acode; row = gw >> 4; w = gw & 15;
    } else {
        gw -= M_TOTAL * NW;
        src = pat; dst = g_Bcode; row = gw >> 4; w = gw & 15;
    }

    float e0 = __ldg(edges + 0), e1 = __ldg(edges + 1), e2 = __ldg(edges + 2),
          e3 = __ldg(edges + 3), e4 = __ldg(edges + 4), e5 = __ldg(edges + 5),
          e6 = __ldg(edges + 6);
    float v = __ldg(src + (size_t)row * D_DIM + w * 32 + lane);
    int q = (v > e0) + (v > e1) + (v > e2) + (v > e3) + (v > e4) + (v > e5) + (v > e6);

    unsigned b0 = __ballot_sync(0xffffffffu, q & 1);
    unsigned b1 = __ballot_sync(0xffffffffu, q & 2);
    unsigned b2 = __ballot_sync(0xffffffffu, q & 4);
    if (lane == 0) {
        int rt = row >> 6, rl = row & 63;
        uint32_t* base = dst + (size_t)rt * TILE_U32 + (w * 3) * TR + rl;
        base[0]      = b0;
        base[TR]     = b1;
        base[2 * TR] = b2;
    }
}

// --------------------------------------------------------------- matcher ----
// CTA = 64M x 64P tile, 256 threads (tx 0..15 p-group, ty 0..15 m-group),
// thread computes 4M x 4P. Register ping-pong pipeline (R7). Accumulation
// via mad.lo.u32 with opaque 'one' -> IMAD on the fma pipe.
__global__ void __launch_bounds__(256) match_kernel(float* __restrict__ out,
                                                    uint32_t one) {
    __shared__ uint32_t sA[TILE_U32];
    __shared__ uint32_t sB[TILE_U32];
    __shared__ bool s_last;

    const int tid = threadIdx.x;
    const int pt = blockIdx.x, mt = blockIdx.y;

    const uint4* gA = reinterpret_cast<const uint4*>(g_Acode + (size_t)mt * TILE_U32);
    const uint4* gB = reinterpret_cast<const uint4*>(g_Bcode + (size_t)pt * TILE_U32);
    uint4* s4A = reinterpret_cast<uint4*>(sA);
    uint4* s4B = reinterpret_cast<uint4*>(sB);
#pragma unroll
    for (int i = 0; i < TILE_U32 / 4; i += 256) {
        s4A[i + tid] = gA[i + tid];
        s4B[i + tid] = gB[i + tid];
    }
    __syncthreads();

    const int tx = tid & 15;
    const int ty = tid >> 4;

    uint32_t acc[4][4];
#pragma unroll
    for (int mi = 0; mi < 4; mi++)
#pragma unroll
        for (int pi = 0; pi < 4; pi++) acc[mi][pi] = 0;

    Frag f0, f1;

    auto load_frag = [&](Frag& f, int w) {
#pragma unroll
        for (int pl = 0; pl < 3; pl++) {
            const int rowbase = (w * 3 + pl) * TR;
            uint4 av = *reinterpret_cast<const uint4*>(&sA[rowbase + ty * 4]);
            f.a[pl][0] = av.x; f.a[pl][1] = av.y; f.a[pl][2] = av.z; f.a[pl][3] = av.w;
            uint4 bv = *reinterpret_cast<const uint4*>(&sB[rowbase + tx * 4]);
            f.b[pl][0] = bv.x; f.b[pl][1] = bv.y; f.b[pl][2] = bv.z; f.b[pl][3] = bv.w;
        }
    };
    auto compute = [&](const Frag& f) {
#pragma unroll
        for (int mi = 0; mi < 4; mi++)
#pragma unroll
            for (int pi = 0; pi < 4; pi++) {
                uint32_t pc = (uint32_t)__popc(
                    eq3(f.a[0][mi], f.b[0][pi], f.a[1][mi], f.b[1][pi],
                        f.a[2][mi], f.b[2][pi]));
                // IMAD (fma pipe): acc += pc * one, 'one' opaque to ptxas.
                asm("mad.lo.u32 %0, %1, %2, %0;"
                    : "+r"(acc[mi][pi]) : "r"(pc), "r"(one));
            }
    };

    load_frag(f0, 0);
#pragma unroll 1
    for (int w = 0; w < NW; w += 2) {
        load_frag(f1, w + 1);        // prefetch w+1, hidden behind compute(w)
        compute(f0);
        load_frag(f0, (w + 2) & 15); // prefetch w+2 (dummy wrap on last iter)
        compute(f1);
    }

    // key = (cnt<<10)|(1023-p): max == first-max (lowest index wins ties).
#pragma unroll
    for (int mi = 0; mi < 4; mi++) {
        uint32_t key = 0;
#pragma unroll
        for (int pi = 0; pi < 4; pi++) {
            int p = pt * TR + tx * 4 + pi;
            uint32_t k = (acc[mi][pi] << 10) | (uint32_t)(1023 - p);
            key = key > k ? key : k;
        }
#pragma unroll
        for (int off = 8; off >= 1; off >>= 1) {   // reduce over the 16 tx lanes
            uint32_t o = __shfl_xor_sync(0xffffffffu, key, off);
            key = key > o ? key : o;
        }
        if (tx == 0) {
            int m = mt * TR + ty * 4 + mi;
            atomicMax(&g_key[m], key);
        }
    }

    // Last CTA converts keys -> (best_patterns, match_scores).
    __threadfence();
    if (tid == 0)
        s_last = (atomicAdd(&g_ctr, 1u) == (unsigned)(NCTAS - 1));
    __syncthreads();
    if (s_last) {
        __threadfence();   // acquire all g_key updates
        for (int m = tid; m < M_TOTAL; m += 256) {
            uint32_t best = g_key[m];
            out[m]           = (float)(1023u - (best & 1023u));
            out[M_TOTAL + m] = (float)(best >> 10) * (1.0f / 512.0f);
        }
    }
}

// ---------------------------------------------------------------- launch ----
extern "C" void kernel_launch(void* const* d_in, const int* in_sizes, int n_in,
                              void* d_out, int out_size) {
    const float* x     = (const float*)d_in[0];
    const float* pat   = (const float*)d_in[1];
    const float* edges = (const float*)d_in[2];

    // (8192 + 1024) rows * 16 words = 147456 warps -> 18432 blocks of 8 warps
    encode_kernel<<<(M_TOTAL + P_TOTAL) * NW / 8, 256>>>(x, pat, edges);
    match_kernel<<<dim3(PT, MT), 256>>>((float*)d_out, 1u);
}

// round 10
// speedup vs baseline: 1.1429x; 1.0285x over previous
#include <cuda_runtime.h>
#include <cuda_bf16.h>
#include <cstdint>

// ============================================================================
// QuantizedPatternMatcher — bit-sliced popcount matcher.
//   q(v) = #edges v exceeds (3-bit code); matches[m,p] = #d q_x==q_pat
// Per u32 word (32 dims): eq = LOP3-chain(a0^b0,a1^b1,a2^b2) -> popc -> mad.
// R9: fully-unrolled match loop, uint4 fragments consumed directly (no MOV
// staging, no loop bookkeeping, immediate-offset LDS). IMAD (fma pipe) for
// accumulate AND key build; alu pipe carries only the 4-op/pair-word floor.
// Argmax exact: key = (cnt<<10)|(1023-p); max == first-max tie-breaking.
// ============================================================================

static constexpr int M_TOTAL = 8192;
static constexpr int P_TOTAL = 1024;
static constexpr int D_DIM   = 512;
static constexpr int NW      = 16;              // u32 words per plane per row
static constexpr int TR      = 64;              // tile rows (both M and P)
static constexpr int MT      = M_TOTAL / TR;    // 128
static constexpr int PT      = P_TOTAL / TR;    // 16
static constexpr int TILE_U32 = NW * 3 * TR;    // 3072 u32 = 12 KB per tile
static constexpr int NCTAS   = MT * PT;         // 2048

__device__ __align__(16) uint32_t g_Acode[MT * TILE_U32];   // 1.5 MB
__device__ __align__(16) uint32_t g_Bcode[PT * TILE_U32];   // 192 KB
__device__ uint32_t g_key[M_TOTAL];
__device__ unsigned int g_ctr;

// NOR-of-xors via guaranteed 3-LOP3 chain.
__device__ __forceinline__ uint32_t eq3(uint32_t a0, uint32_t b0,
                                        uint32_t a1, uint32_t b1,
                                        uint32_t a2, uint32_t b2) {
    uint32_t x, y, z;
    asm("lop3.b32 %0, %1, %2, %3, 0x3C;" : "=r"(x) : "r"(a0), "r"(b0), "r"(0u)); // a^b
    asm("lop3.b32 %0, %1, %2, %3, 0xBE;" : "=r"(y) : "r"(a1), "r"(b1), "r"(x));  // (a^b)|c
    asm("lop3.b32 %0, %1, %2, %3, 0x41;" : "=r"(z) : "r"(a2), "r"(b2), "r"(y));  // ~((a^b)|c)
    return z;
}

// ------------------------------------------------------------- encoding ----
// One warp per (row, word). Ballots build 3 bitplanes. Tile layout
// [tile][w][plane][row_local(64)] -> match kernel copies are uint4 streams.
// Block 0 additionally zeroes g_key / g_ctr for this replay.
__global__ void __launch_bounds__(256) encode_kernel(
    const float* __restrict__ x, const float* __restrict__ pat,
    const float* __restrict__ edges) {
    if (blockIdx.x == 0) {
        for (int i = threadIdx.x; i < M_TOTAL; i += 256) g_key[i] = 0u;
        if (threadIdx.x == 0) g_ctr = 0u;
    }
    int gw   = blockIdx.x * 8 + (threadIdx.x >> 5);
    int lane = threadIdx.x & 31;

    const float* src;
    uint32_t* dst;
    int row, w;
    if (gw < M_TOTAL * NW) {
        src = x;   dst = g_Acode; row = gw >> 4; w = gw & 15;
    } else {
        gw -= M_TOTAL * NW;
        src = pat; dst = g_Bcode; row = gw >> 4; w = gw & 15;
    }

    float e0 = __ldg(edges + 0), e1 = __ldg(edges + 1), e2 = __ldg(edges + 2),
          e3 = __ldg(edges + 3), e4 = __ldg(edges + 4), e5 = __ldg(edges + 5),
          e6 = __ldg(edges + 6);
    float v = __ldg(src + (size_t)row * D_DIM + w * 32 + lane);
    int q = (v > e0) + (v > e1) + (v > e2) + (v > e3) + (v > e4) + (v > e5) + (v > e6);

    unsigned b0 = __ballot_sync(0xffffffffu, q & 1);
    unsigned b1 = __ballot_sync(0xffffffffu, q & 2);
    unsigned b2 = __ballot_sync(0xffffffffu, q & 4);
    if (lane == 0) {
        int rt = row >> 6, rl = row & 63;
        uint32_t* base = dst + (size_t)rt * TILE_U32 + (w * 3) * TR + rl;
        base[0]      = b0;
        base[TR]     = b1;
        base[2 * TR] = b2;
    }
}

// --------------------------------------------------------------- matcher ----
// CTA = 64M x 64P tile, 256 threads (tx 0..15 p-group, ty 0..15 m-group),
// thread computes 4M x 4P. Fully unrolled word loop; fragments held as uint4
// and consumed field-wise so no MOV staging survives; all LDS use immediate
// offsets from two base pointers. acc and key via IMAD on the fma pipe.
__global__ void __launch_bounds__(256) match_kernel(float* __restrict__ out,
                                                    uint32_t one) {
    __shared__ uint32_t sA[TILE_U32];
    __shared__ uint32_t sB[TILE_U32];
    __shared__ bool s_last;

    const int tid = threadIdx.x;
    const int pt = blockIdx.x, mt = blockIdx.y;

    const uint4* gA = reinterpret_cast<const uint4*>(g_Acode + (size_t)mt * TILE_U32);
    const uint4* gB = reinterpret_cast<const uint4*>(g_Bcode + (size_t)pt * TILE_U32);
    uint4* s4A = reinterpret_cast<uint4*>(sA);
    uint4* s4B = reinterpret_cast<uint4*>(sB);
#pragma unroll
    for (int i = 0; i < TILE_U32 / 4; i += 256) {
        s4A[i + tid] = gA[i + tid];
        s4B[i + tid] = gB[i + tid];
    }
    __syncthreads();

    const int tx = tid & 15;
    const int ty = tid >> 4;

    // Base pointers; every load below is [base + compile-time-imm].
    const uint4* baseA = reinterpret_cast<const uint4*>(&sA[ty * 4]);
    const uint4* baseB = reinterpret_cast<const uint4*>(&sB[tx * 4]);

    uint32_t acc[4][4];
#pragma unroll
    for (int mi = 0; mi < 4; mi++)
#pragma unroll
        for (int pi = 0; pi < 4; pi++) acc[mi][pi] = 0;

#pragma unroll
    for (int w = 0; w < NW; w++) {
        // (w*3+pl)*TR u32 = (w*3+pl)*16 uint4 — all immediates after unroll.
        const uint4 a0 = baseA[(w * 3 + 0) * 16];
        const uint4 a1 = baseA[(w * 3 + 1) * 16];
        const uint4 a2 = baseA[(w * 3 + 2) * 16];
        const uint4 b0 = baseB[(w * 3 + 0) * 16];
        const uint4 b1 = baseB[(w * 3 + 1) * 16];
        const uint4 b2 = baseB[(w * 3 + 2) * 16];

        const uint32_t am0[4] = {a0.x, a0.y, a0.z, a0.w};
        const uint32_t am1[4] = {a1.x, a1.y, a1.z, a1.w};
        const uint32_t am2[4] = {a2.x, a2.y, a2.z, a2.w};
        const uint32_t bp0[4] = {b0.x, b0.y, b0.z, b0.w};
        const uint32_t bp1[4] = {b1.x, b1.y, b1.z, b1.w};
        const uint32_t bp2[4] = {b2.x, b2.y, b2.z, b2.w};

#pragma unroll
        for (int mi = 0; mi < 4; mi++)
#pragma unroll
            for (int pi = 0; pi < 4; pi++) {
                uint32_t pc = (uint32_t)__popc(
                    eq3(am0[mi], bp0[pi], am1[mi], bp1[pi], am2[mi], bp2[pi]));
                // IMAD on fma pipe: acc += pc * one ('one' opaque, ==1).
                asm("mad.lo.u32 %0, %1, %2, %0;"
                    : "+r"(acc[mi][pi]) : "r"(pc), "r"(one));
            }
    }

    // key = cnt*1024 + (1023-p) via IMAD: max == first-max (lowest p wins).
#pragma unroll
    for (int mi = 0; mi < 4; mi++) {
        uint32_t key = 0;
#pragma unroll
        for (int pi = 0; pi < 4; pi++) {
            uint32_t inv = (uint32_t)(1023 - (pt * TR + tx * 4 + pi));
            uint32_t k;
            asm("mad.lo.u32 %0, %1, %2, %3;"
                : "=r"(k) : "r"(acc[mi][pi]), "r"(1024u * one), "r"(inv));
            key = key > k ? key : k;
        }
#pragma unroll
        for (int off = 8; off >= 1; off >>= 1) {   // reduce over the 16 tx lanes
            uint32_t o = __shfl_xor_sync(0xffffffffu, key, off);
            key = key > o ? key : o;
        }
        if (tx == 0) {
            int m = mt * TR + ty * 4 + mi;
            atomicMax(&g_key[m], key);
        }
    }

    // Last CTA converts keys -> (best_patterns, match_scores).
    __threadfence();
    if (tid == 0)
        s_last = (atomicAdd(&g_ctr, 1u) == (unsigned)(NCTAS - 1));
    __syncthreads();
    if (s_last) {
        __threadfence();   // acquire all g_key updates
        for (int m = tid; m < M_TOTAL; m += 256) {
            uint32_t best = g_key[m];
            out[m]           = (float)(1023u - (best & 1023u));
            out[M_TOTAL + m] = (float)(best >> 10) * (1.0f / 512.0f);
        }
    }
}

// ---------------------------------------------------------------- launch ----
extern "C" void kernel_launch(void* const* d_in, const int* in_sizes, int n_in,
                              void* d_out, int out_size) {
    const float* x     = (const float*)d_in[0];
    const float* pat   = (const float*)d_in[1];
    const float* edges = (const float*)d_in[2];

    // (8192 + 1024) rows * 16 words = 147456 warps -> 18432 blocks of 8 warps
    encode_kernel<<<(M_TOTAL + P_TOTAL) * NW / 8, 256>>>(x, pat, edges);
    match_kernel<<<dim3(PT, MT), 256>>>((float*)d_out, 1u);
}

// round 11
// speedup vs baseline: 1.2196x; 1.0671x over previous
#include <cuda_runtime.h>
#include <cuda_bf16.h>
#include <cstdint>

// ============================================================================
// QuantizedPatternMatcher — bit-sliced popcount matcher, single persistent
// kernel (R10): encode (float4 + 12-ballot, dim-permuted words) -> barrier ->
// R9 match loop (full unroll, IMAD accumulate/keys on fma pipe) -> barrier ->
// output. One launch: kills encode-kernel wall + one graph-launch fixed cost.
//   q(v) = #edges v exceeds (3-bit code); matches[m,p] = #d q_x==q_pat
// Per u32 word: eq = 3xLOP3 -> POPC (alu floor) -> IMAD (fma pipe).
// Argmax exact: key = cnt*1024 + (1023-p); max == first-max tie-breaking.
// ============================================================================

static constexpr int M_TOTAL = 8192;
static constexpr int P_TOTAL = 1024;
static constexpr int D_DIM   = 512;
static constexpr int NW      = 16;              // u32 words per plane per row
static constexpr int TR      = 64;              // tile rows (both M and P)
static constexpr int MT      = M_TOTAL / TR;    // 128
static constexpr int PT      = P_TOTAL / TR;    // 16
static constexpr int TILE_U32 = NW * 3 * TR;    // 3072 u32 = 12 KB per tile
static constexpr int NTILES  = MT * PT;         // 2048
static constexpr int NCTA    = 592;             // 4/SM x 148 SMs, all resident
static constexpr int ENC_JOBS = (M_TOTAL + P_TOTAL) * D_DIM / 128;  // 36864

__device__ __align__(16) uint32_t g_Acode[MT * TILE_U32];   // 1.5 MB
__device__ __align__(16) uint32_t g_Bcode[PT * TILE_U32];   // 192 KB
__device__ uint32_t g_key[M_TOTAL];
__device__ unsigned g_bar1, g_bar2, g_fin;
__device__ volatile unsigned g_go1, g_go2;

// NOR-of-xors via guaranteed 3-LOP3 chain.
__device__ __forceinline__ uint32_t eq3(uint32_t a0, uint32_t b0,
                                        uint32_t a1, uint32_t b1,
                                        uint32_t a2, uint32_t b2) {
    uint32_t x, y, z;
    asm("lop3.b32 %0, %1, %2, %3, 0x3C;" : "=r"(x) : "r"(a0), "r"(b0), "r"(0u)); // a^b
    asm("lop3.b32 %0, %1, %2, %3, 0xBE;" : "=r"(y) : "r"(a1), "r"(b1), "r"(x));  // (a^b)|c
    asm("lop3.b32 %0, %1, %2, %3, 0x41;" : "=r"(z) : "r"(a2), "r"(b2), "r"(y));  // ~((a^b)|c)
    return z;
}

// Device-wide barrier across all NCTA resident CTAs (R6-proven pattern).
__device__ __forceinline__ void grid_barrier(unsigned* ctr, volatile unsigned* flag,
                                             int tid) {
    __syncthreads();
    __threadfence();
    if (tid == 0) {
        if (atomicAdd(ctr, 1u) + 1u == (unsigned)NCTA)
            atomicExch((unsigned*)flag, 1u);
        while (*flag == 0u) __nanosleep(64);
    }
    __syncthreads();
    __threadfence();
}

__global__ void __launch_bounds__(256, 4) fused_kernel(
    const float* __restrict__ x, const float* __restrict__ pat,
    const float* __restrict__ edges, float* __restrict__ out, uint32_t one) {
    __shared__ uint32_t sA[TILE_U32];
    __shared__ uint32_t sB[TILE_U32];

    const int tid  = threadIdx.x;
    const int cta  = blockIdx.x;
    const int lane = tid & 31;

    // ---- phase 0: zero argmax keys (sliced across CTAs) ----
    for (int i = cta * 256 + tid; i < M_TOTAL; i += NCTA * 256) g_key[i] = 0u;

    // ---- phase 1: encode. Warp-job = (row, 128-dim quarter). Thread loads a
    // float4; 12 ballots build 3 planes x 4 words. Word (c*4+j, plane pl) has
    // bit t = dim 128c+4t+j — a fixed permutation, identical for A and B, so
    // positional match counting is unaffected. ----
    {
        const float e0 = __ldg(edges + 0), e1 = __ldg(edges + 1),
                    e2 = __ldg(edges + 2), e3 = __ldg(edges + 3),
                    e4 = __ldg(edges + 4), e5 = __ldg(edges + 5),
                    e6 = __ldg(edges + 6);
        for (int job = cta * 8 + (tid >> 5); job < ENC_JOBS; job += NCTA * 8) {
            const int r = job >> 2, c = job & 3;
            const float* src;
            uint32_t* dstbase;
            int rr;
            if (r < M_TOTAL) { src = x;   dstbase = g_Acode; rr = r; }
            else             { src = pat; dstbase = g_Bcode; rr = r - M_TOTAL; }

            float4 v = __ldg(reinterpret_cast<const float4*>(
                src + (size_t)rr * D_DIM + c * 128 + lane * 4));
            int q[4];
            q[0] = (v.x > e0) + (v.x > e1) + (v.x > e2) + (v.x > e3) +
                   (v.x > e4) + (v.x > e5) + (v.x > e6);
            q[1] = (v.y > e0) + (v.y > e1) + (v.y > e2) + (v.y > e3) +
                   (v.y > e4) + (v.y > e5) + (v.y > e6);
            q[2] = (v.z > e0) + (v.z > e1) + (v.z > e2) + (v.z > e3) +
                   (v.z > e4) + (v.z > e5) + (v.z > e6);
            q[3] = (v.w > e0) + (v.w > e1) + (v.w > e2) + (v.w > e3) +
                   (v.w > e4) + (v.w > e5) + (v.w > e6);

            // addr(j,pl) = base + (12c + 3j + pl)*TR, k = 3j+pl stored by lane k
            uint32_t* base = dstbase + (size_t)(rr >> 6) * TILE_U32 +
                             (rr & 63) + c * 12 * TR;
#pragma unroll
            for (int j = 0; j < 4; j++)
#pragma unroll
                for (int pl = 0; pl < 3; pl++) {
                    unsigned b = __ballot_sync(0xffffffffu, (q[j] >> pl) & 1);
                    const int k = j * 3 + pl;
                    if (lane == k) base[k * TR] = b;
                }
        }
    }

    grid_barrier(&g_bar1, &g_go1, tid);

    // ---- phase 2: match tiles [t0,t1), m-major so sA reused across pt ----
    const int t0 = (cta * NTILES) / NCTA;
    const int t1 = ((cta + 1) * NTILES) / NCTA;
    const int tx = tid & 15;
    const int ty = tid >> 4;
    int cur_mt = -1;

    for (int t = t0; t < t1; t++) {
        const int mt = t >> 4, pt = t & 15;

        __syncthreads();   // previous tile's compute done before smem overwrite
        if (mt != cur_mt) {   // uniform branch
            const uint4* gA = reinterpret_cast<const uint4*>(g_Acode + (size_t)mt * TILE_U32);
            uint4* s4A = reinterpret_cast<uint4*>(sA);
#pragma unroll
            for (int i = 0; i < TILE_U32 / 4; i += 256) s4A[i + tid] = gA[i + tid];
            cur_mt = mt;
        }
        {
            const uint4* gB = reinterpret_cast<const uint4*>(g_Bcode + (size_t)pt * TILE_U32);
            uint4* s4B = reinterpret_cast<uint4*>(sB);
#pragma unroll
            for (int i = 0; i < TILE_U32 / 4; i += 256) s4B[i + tid] = gB[i + tid];
        }
        __syncthreads();

        // Base pointers; every load below is [base + compile-time-imm].
        const uint4* baseA = reinterpret_cast<const uint4*>(&sA[ty * 4]);
        const uint4* baseB = reinterpret_cast<const uint4*>(&sB[tx * 4]);

        uint32_t acc[4][4];
#pragma unroll
        for (int mi = 0; mi < 4; mi++)
#pragma unroll
            for (int pi = 0; pi < 4; pi++) acc[mi][pi] = 0;

#pragma unroll
        for (int w = 0; w < NW; w++) {
            const uint4 a0 = baseA[(w * 3 + 0) * 16];
            const uint4 a1 = baseA[(w * 3 + 1) * 16];
            const uint4 a2 = baseA[(w * 3 + 2) * 16];
            const uint4 b0 = baseB[(w * 3 + 0) * 16];
            const uint4 b1 = baseB[(w * 3 + 1) * 16];
            const uint4 b2 = baseB[(w * 3 + 2) * 16];

            const uint32_t am0[4] = {a0.x, a0.y, a0.z, a0.w};
            const uint32_t am1[4] = {a1.x, a1.y, a1.z, a1.w};
            const uint32_t am2[4] = {a2.x, a2.y, a2.z, a2.w};
            const uint32_t bp0[4] = {b0.x, b0.y, b0.z, b0.w};
            const uint32_t bp1[4] = {b1.x, b1.y, b1.z, b1.w};
            const uint32_t bp2[4] = {b2.x, b2.y, b2.z, b2.w};

#pragma unroll
            for (int mi = 0; mi < 4; mi++)
#pragma unroll
                for (int pi = 0; pi < 4; pi++) {
                    uint32_t pc = (uint32_t)__popc(
                        eq3(am0[mi], bp0[pi], am1[mi], bp1[pi], am2[mi], bp2[pi]));
                    asm("mad.lo.u32 %0, %1, %2, %0;"
                        : "+r"(acc[mi][pi]) : "r"(pc), "r"(one));
                }
        }

        // key = cnt*1024 + (1023-p): max == first-max (lowest p wins ties).
#pragma unroll
        for (int mi = 0; mi < 4; mi++) {
            uint32_t key = 0;
#pragma unroll
            for (int pi = 0; pi < 4; pi++) {
                uint32_t inv = (uint32_t)(1023 - (pt * TR + tx * 4 + pi));
                uint32_t k;
                asm("mad.lo.u32 %0, %1, %2, %3;"
                    : "=r"(k) : "r"(acc[mi][pi]), "r"(1024u * one), "r"(inv));
                key = key > k ? key : k;
            }
#pragma unroll
            for (int off = 8; off >= 1; off >>= 1) {
                uint32_t o = __shfl_xor_sync(0xffffffffu, key, off);
                key = key > o ? key : o;
            }
            if (tx == 0)
                atomicMax(&g_key[mt * TR + ty * 4 + mi], key);
        }
    }

    grid_barrier(&g_bar2, &g_go2, tid);

    // ---- phase 3: write outputs (sliced across CTAs) ----
    for (int m = cta * 256 + tid; m < M_TOTAL; m += NCTA * 256) {
        uint32_t best = g_key[m];
        out[m]           = (float)(1023u - (best & 1023u));          // best_patterns
        out[M_TOTAL + m] = (float)(best >> 10) * (1.0f / 512.0f);    // match_scores
    }

    // ---- cleanup: last CTA resets barrier state for the next graph replay ----
    __syncthreads();
    if (tid == 0) {
        if (atomicAdd(&g_fin, 1u) + 1u == (unsigned)NCTA) {
            g_bar1 = 0u; g_bar2 = 0u; g_fin = 0u;
            g_go1 = 0u;  g_go2 = 0u;
            __threadfence();
        }
    }
}

// ---------------------------------------------------------------- launch ----
extern "C" void kernel_launch(void* const* d_in, const int* in_sizes, int n_in,
                              void* d_out, int out_size) {
    const float* x     = (const float*)d_in[0];
    const float* pat   = (const float*)d_in[1];
    const float* edges = (const float*)d_in[2];

    fused_kernel<<<NCTA, 256>>>(x, pat, edges, (float*)d_out, 1u);
}